// round 9
// baseline (speedup 1.0000x reference)
#include <cuda_runtime.h>
#include <cuda_bf16.h>
#include <math.h>
#include <stdint.h>

// Problem constants
#define PB 4
#define PS 2048
#define PD 1024
#define PH 16
#define PDH 64

// ---------------------------------------------------------------------------
// Scratch (device globals — no allocations allowed)
// ---------------------------------------------------------------------------
__device__ float g_q[PB*PH*PS*PDH];     // [b*H+h][s][dh]
__device__ float g_k[PB*PH*PS*PDH];
__device__ float g_v[PB*PH*PS*PDH];
__device__ float g_cos[PS*32];
__device__ float g_sin[PS*32];

// bf16 split operands for tensor-core GEMMs
__device__ __nv_bfloat16 g_xh[8192*1024], g_xl[8192*1024];      // x
__device__ __nv_bfloat16 g_wqh[3072*1024], g_wql[3072*1024];    // W_qkv
__device__ __nv_bfloat16 g_woh[1024*1024], g_wol[1024*1024];    // W_o
__device__ __nv_bfloat16 g_ah[8192*1024], g_al[8192*1024];      // attn out (written by flash)

// ---------------------------------------------------------------------------
// Portable PTX helpers (toolchain targets base compute_103: no tcgen05/TMEM)
// ---------------------------------------------------------------------------
__device__ __forceinline__ uint32_t smem_u32(const void* p) {
    uint32_t a;
    asm("{ .reg .u64 t; cvta.to.shared.u64 t, %1; cvt.u32.u64 %0, t; }"
        : "=r"(a) : "l"(p));
    return a;
}

__device__ __forceinline__ void cp16(uint32_t saddr, const void* gaddr) {
    asm volatile("cp.async.cg.shared.global [%0], [%1], 16;"
                 :: "r"(saddr), "l"(gaddr) : "memory");
}
#define CP_COMMIT() asm volatile("cp.async.commit_group;" ::: "memory")
#define CP_WAIT0()  asm volatile("cp.async.wait_group 0;" ::: "memory")
#define CP_WAIT1()  asm volatile("cp.async.wait_group 1;" ::: "memory")

__device__ __forceinline__ void ldm_x4(uint32_t* r, uint32_t addr) {
    asm volatile("ldmatrix.sync.aligned.m8n8.x4.shared.b16 {%0,%1,%2,%3}, [%4];"
        : "=r"(r[0]), "=r"(r[1]), "=r"(r[2]), "=r"(r[3]) : "r"(addr));
}

__device__ __forceinline__ void mma16816(float* d, const uint32_t* a, const uint32_t* b) {
    asm volatile(
        "mma.sync.aligned.m16n8k16.row.col.f32.bf16.bf16.f32 "
        "{%0,%1,%2,%3}, {%4,%5,%6,%7}, {%8,%9}, {%0,%1,%2,%3};"
        : "+f"(d[0]), "+f"(d[1]), "+f"(d[2]), "+f"(d[3])
        : "r"(a[0]), "r"(a[1]), "r"(a[2]), "r"(a[3]), "r"(b[0]), "r"(b[1]));
}

// ---------------------------------------------------------------------------
// Fast exp on FMA/ALU pipes (NO MUFU). Valid for x <= ~0 (softmax args).
// exp(x) = 2^n * e^r, n = round(x*log2e), r = x - n*ln2, |r| <= 0.347.
// Degree-5 Taylor: rel err <= 3e-6. Clamp at -87 -> exp ~ 0 for masked lanes.
// ---------------------------------------------------------------------------
__device__ __forceinline__ float fexp(float x) {
    float xc = fmaxf(x, -87.0f);
    float t  = fmaf(xc, 1.4426950408889634f, 12582912.0f);  // round(x*log2e) in mantissa
    float n  = t - 12582912.0f;
    float r  = fmaf(n, -0.6931471805599453f, xc);
    float p  = 8.3333333e-3f;                                // 1/120
    p = fmaf(p, r, 4.1666667e-2f);                           // 1/24
    p = fmaf(p, r, 1.6666667e-1f);                           // 1/6
    p = fmaf(p, r, 5.0e-1f);
    p = fmaf(p, r, 1.0f);
    p = fmaf(p, r, 1.0f);
    float s = __int_as_float((__float_as_int(t) << 23) + 0x3f800000);
    return p * s;
}

// ---------------------------------------------------------------------------
// RoPE table (fp64 for fidelity)
// ---------------------------------------------------------------------------
__global__ void rope_table_kernel(const int* __restrict__ pos) {
    int idx = blockIdx.x * blockDim.x + threadIdx.x;   // 65536
    int s = idx >> 5;
    int i = idx & 31;
    double p = (double)pos[s];
    double inv = exp(-((double)(2 * i) / 64.0) * log(10000.0));
    double a = p * inv;
    g_cos[idx] = (float)cos(a);
    g_sin[idx] = (float)sin(a);
}

// ---------------------------------------------------------------------------
// fp32 -> bf16 hi/lo split (2-term); 4 elems/thread
// ---------------------------------------------------------------------------
__device__ __forceinline__ void split4(const float* __restrict__ src,
                                       __nv_bfloat16* __restrict__ hi,
                                       __nv_bfloat16* __restrict__ lo) {
    int i = blockIdx.x * blockDim.x + threadIdx.x;
    float4 v = ((const float4*)src)[i];
    __nv_bfloat16 h0 = __float2bfloat16(v.x);
    __nv_bfloat16 h1 = __float2bfloat16(v.y);
    __nv_bfloat16 h2 = __float2bfloat16(v.z);
    __nv_bfloat16 h3 = __float2bfloat16(v.w);
    __nv_bfloat16 l0 = __float2bfloat16(v.x - __bfloat162float(h0));
    __nv_bfloat16 l1 = __float2bfloat16(v.y - __bfloat162float(h1));
    __nv_bfloat16 l2 = __float2bfloat16(v.z - __bfloat162float(h2));
    __nv_bfloat16 l3 = __float2bfloat16(v.w - __bfloat162float(h3));
    ((__nv_bfloat162*)hi)[i*2]   = __halves2bfloat162(h0, h1);
    ((__nv_bfloat162*)hi)[i*2+1] = __halves2bfloat162(h2, h3);
    ((__nv_bfloat162*)lo)[i*2]   = __halves2bfloat162(l0, l1);
    ((__nv_bfloat162*)lo)[i*2+1] = __halves2bfloat162(l2, l3);
}

__global__ void split_x_kernel(const float* __restrict__ x)  { split4(x, g_xh, g_xl); }
__global__ void split_wq_kernel(const float* __restrict__ w) { split4(w, g_wqh, g_wql); }
__global__ void split_wo_kernel(const float* __restrict__ w) { split4(w, g_woh, g_wol); }

// ---------------------------------------------------------------------------
// mma.sync bf16 GEMM, 128x128 CTA tile, BK=32, 256 threads,
// 2-stage cp.async pipeline (double-buffered smem, 80 KB dynamic).
// C[m][n] = sum_k A[m][k]*B[n][k], 3-term split: AhBh + AhBl + AlBh, fp32 acc.
// MODE 0: A=x, B=W_qkv, epilogue RoPE+scatter into g_q/g_k/g_v.
// MODE 1: A=attn(bf16 split), B=W_o, epilogue plain store into Cout.
// ---------------------------------------------------------------------------
#define LDT 40            // smem row stride (bf16); 80B rows -> conflict-free ldmatrix
#define TILE_B (128*LDT*2)        // 10240 B per tile
#define STAGE_B (4*TILE_B)        // Ah,Al,Bh,Bl per stage = 40960 B
#define GEMM_SMEM (2*STAGE_B)     // 81920 B

template<int MODE>
__global__ __launch_bounds__(256)
void mma_gemm_kernel(float* __restrict__ Cout)
{
    const __nv_bfloat16 *Ahp, *Alp, *Bhp, *Blp;
    if (MODE == 0) { Ahp = g_xh; Alp = g_xl; Bhp = g_wqh; Blp = g_wql; }
    else           { Ahp = g_ah; Alp = g_al; Bhp = g_woh; Blp = g_wol; }

    extern __shared__ char dsm[];
    const uint32_t sBase = smem_u32(dsm);

    const int tid = threadIdx.x;
    const int n0 = blockIdx.x * 128;
    const int m0 = blockIdx.y * 128;
    const int lane = tid & 31, w = tid >> 5;
    const int wm = w >> 2, wn = w & 3;

    const int lr = tid >> 1, lh = tid & 1;
    const __nv_bfloat16* gAh = Ahp + (size_t)(m0 + lr) * 1024 + lh * 16;
    const __nv_bfloat16* gAl = Alp + (size_t)(m0 + lr) * 1024 + lh * 16;
    const __nv_bfloat16* gBh = Bhp + (size_t)(n0 + lr) * 1024 + lh * 16;
    const __nv_bfloat16* gBl = Blp + (size_t)(n0 + lr) * 1024 + lh * 16;
    const uint32_t sOff = (uint32_t)((lr * LDT + lh * 16) * 2);

    const int quad = lane >> 3, qi = lane & 7;
    const uint32_t aoff = (uint32_t)(((wm*64 + (quad&1)*8 + qi) * LDT + (quad>>1)*8) * 2);
    const uint32_t boff = (uint32_t)(((wn*32 + (quad>>1)*8 + qi) * LDT + (quad&1)*8) * 2);

    float acc[4][4][4];
#pragma unroll
    for (int a = 0; a < 4; a++)
#pragma unroll
        for (int b = 0; b < 4; b++)
#pragma unroll
            for (int c = 0; c < 4; c++) acc[a][b][c] = 0.0f;

    auto load_stage = [&](int kt, int stg) {
        const int kb = kt * 32;
        const uint32_t s0 = sBase + stg * STAGE_B + sOff;
        cp16(s0,                    gAh + kb);  cp16(s0 + 16,              gAh + kb + 8);
        cp16(s0 + TILE_B,           gAl + kb);  cp16(s0 + TILE_B + 16,     gAl + kb + 8);
        cp16(s0 + 2*TILE_B,         gBh + kb);  cp16(s0 + 2*TILE_B + 16,   gBh + kb + 8);
        cp16(s0 + 3*TILE_B,         gBl + kb);  cp16(s0 + 3*TILE_B + 16,   gBl + kb + 8);
        CP_COMMIT();
    };

    load_stage(0, 0);

    for (int kt = 0; kt < 32; kt++) {
        const int stg = kt & 1;
        if (kt + 1 < 32) {
            load_stage(kt + 1, stg ^ 1);
            CP_WAIT1();
        } else {
            CP_WAIT0();
        }
        __syncthreads();

        const uint32_t sAhB = sBase + stg * STAGE_B;
        const uint32_t sAlB = sAhB + TILE_B;
        const uint32_t sBhB = sAhB + 2*TILE_B;
        const uint32_t sBlB = sAhB + 3*TILE_B;

#pragma unroll
        for (int ks = 0; ks < 2; ks++) {
            const uint32_t kso = ks * 32;
            uint32_t aH[4][4], aL[4][4], bH[2][4], bL[2][4];
#pragma unroll
            for (int mt = 0; mt < 4; mt++) {
                ldm_x4(aH[mt], sAhB + aoff + mt * (16*LDT*2) + kso);
                ldm_x4(aL[mt], sAlB + aoff + mt * (16*LDT*2) + kso);
            }
#pragma unroll
            for (int np = 0; np < 2; np++) {
                ldm_x4(bH[np], sBhB + boff + np * (16*LDT*2) + kso);
                ldm_x4(bL[np], sBlB + boff + np * (16*LDT*2) + kso);
            }
#pragma unroll
            for (int mt = 0; mt < 4; mt++)
#pragma unroll
                for (int nt = 0; nt < 4; nt++) {
                    const uint32_t* ph = &bH[nt >> 1][(nt & 1) * 2];
                    const uint32_t* pl = &bL[nt >> 1][(nt & 1) * 2];
                    mma16816(acc[mt][nt], aH[mt], ph);
                    mma16816(acc[mt][nt], aH[mt], pl);
                    mma16816(acc[mt][nt], aL[mt], ph);
                }
        }
        __syncthreads();
    }

    const int g = lane >> 2, tig = lane & 3;
    if (MODE == 0) {
        const int kmat = n0 >> 10;                   // 0=q 1=k 2=v
        float* dst = (kmat == 0) ? g_q : ((kmat == 1) ? g_k : g_v);
#pragma unroll
        for (int mt = 0; mt < 4; mt++)
#pragma unroll
            for (int hh = 0; hh < 2; hh++) {
                const int m = m0 + wm*64 + mt*16 + hh*8 + g;
                const int b = m >> 11, s = m & 2047;
#pragma unroll
                for (int nt = 0; nt < 4; nt++) {
                    const int colg = n0 + wn*32 + nt*8 + 2*tig;
                    const int h = (colg >> 6) & 15;
                    const int cc = colg & 63;
                    const float v0 = acc[mt][nt][hh*2];
                    const float v1 = acc[mt][nt][hh*2 + 1];
                    float2 r;
                    if (kmat < 2) {
                        const int pi = (s << 5) + (cc >> 1);
                        const float c_ = g_cos[pi], s_ = g_sin[pi];
                        r.x = v0 * c_ - v1 * s_;
                        r.y = v0 * s_ + v1 * c_;
                    } else {
                        r.x = v0; r.y = v1;
                    }
                    *(float2*)(dst + ((size_t)((b*PH + h)*PS + s))*PDH + cc) = r;
                }
            }
    } else {
#pragma unroll
        for (int mt = 0; mt < 4; mt++)
#pragma unroll
            for (int hh = 0; hh < 2; hh++) {
                const int m = m0 + wm*64 + mt*16 + hh*8 + g;
#pragma unroll
                for (int nt = 0; nt < 4; nt++) {
                    const int colg = n0 + wn*32 + nt*8 + 2*tig;
                    float2 r;
                    r.x = acc[mt][nt][hh*2];
                    r.y = acc[mt][nt][hh*2 + 1];
                    *(float2*)(Cout + (size_t)m * 1024 + colg) = r;
                }
            }
    }
}

// ---------------------------------------------------------------------------
// Flash attention, fp32 math; exp on FMA pipe (fexp); writes bf16 hi/lo
// splits of the attention output directly (no fp32 g_attn round-trip).
// ---------------------------------------------------------------------------
__global__ __launch_bounds__(256) void flash_attn_kernel() {
    extern __shared__ float sm[];
    float* Qs = sm;                  // 64*68
    float* Ks = sm + 64 * 68;        // 64*68
    float* Vs = Ks + 64 * 68;        // 64*64
    float* Ps = Vs + 64 * 64;        // 64*68

    const int tid = threadIdx.x;
    const int tx = tid & 15;
    const int ty = tid >> 4;
    const int qb = blockIdx.x;
    const int bh = blockIdx.y;

    const float* Qg  = g_q + ((size_t)bh * PS + qb * 64) * PDH;
    const float* Kg0 = g_k + (size_t)bh * PS * PDH;
    const float* Vg0 = g_v + (size_t)bh * PS * PDH;

    {
        int row = tid & 63;
        int c4b = tid >> 6;
        float4 t[4];
#pragma unroll
        for (int p = 0; p < 4; p++) {
            int c4 = c4b + p * 4;
            t[p] = *(const float4*)(Qg + row * 64 + c4 * 4);
        }
#pragma unroll
        for (int p = 0; p < 4; p++) {
            int c4 = c4b + p * 4;
            Qs[(c4*4+0)*68 + row] = t[p].x;
            Qs[(c4*4+1)*68 + row] = t[p].y;
            Qs[(c4*4+2)*68 + row] = t[p].z;
            Qs[(c4*4+3)*68 + row] = t[p].w;
        }
    }

    float o[4][4];
    float mrow[4], lrow[4];
#pragma unroll
    for (int i = 0; i < 4; i++) {
        mrow[i] = -1e30f; lrow[i] = 0.0f;
#pragma unroll
        for (int j = 0; j < 4; j++) o[i][j] = 0.0f;
    }

    for (int j = 0; j <= qb; j++) {
        const float* Kg = Kg0 + j * 64 * 64;
        const float* Vg = Vg0 + j * 64 * 64;
        int row = tid & 63;
        int c4b = tid >> 6;
        float4 kt[4], vt[4];
#pragma unroll
        for (int p = 0; p < 4; p++) {
            int c4 = c4b + p * 4;
            kt[p] = *(const float4*)(Kg + row * 64 + c4 * 4);
            int f = tid + 256 * p;
            vt[p] = *(const float4*)(Vg + (f >> 4) * 64 + (f & 15) * 4);
        }
        __syncthreads();
#pragma unroll
        for (int p = 0; p < 4; p++) {
            int c4 = c4b + p * 4;
            Ks[(c4*4+0)*68 + row] = kt[p].x;
            Ks[(c4*4+1)*68 + row] = kt[p].y;
            Ks[(c4*4+2)*68 + row] = kt[p].z;
            Ks[(c4*4+3)*68 + row] = kt[p].w;
            int f = tid + 256 * p;
            *(float4*)&Vs[(f >> 4) * 64 + (f & 15) * 4] = vt[p];
        }
        __syncthreads();

        float sc[4][4];
#pragma unroll
        for (int i = 0; i < 4; i++)
#pragma unroll
            for (int jj = 0; jj < 4; jj++) sc[i][jj] = 0.0f;
#pragma unroll 8
        for (int d = 0; d < 64; d++) {
            float4 q4 = *(const float4*)&Qs[d * 68 + ty * 4];
            float4 k4 = *(const float4*)&Ks[d * 68 + tx * 4];
            float qa[4] = {q4.x, q4.y, q4.z, q4.w};
            float ka[4] = {k4.x, k4.y, k4.z, k4.w};
#pragma unroll
            for (int i = 0; i < 4; i++)
#pragma unroll
                for (int jj = 0; jj < 4; jj++) sc[i][jj] += qa[i] * ka[jj];
        }
        if (j == qb) {
#pragma unroll
            for (int i = 0; i < 4; i++) {
                int qg = qb * 64 + ty * 4 + i;
#pragma unroll
                for (int jj = 0; jj < 4; jj++) {
                    int kg = j * 64 + tx * 4 + jj;
                    sc[i][jj] = (kg > qg) ? -1e30f : sc[i][jj] * 0.125f;
                }
            }
        } else {
#pragma unroll
            for (int i = 0; i < 4; i++)
#pragma unroll
                for (int jj = 0; jj < 4; jj++) sc[i][jj] *= 0.125f;
        }

#pragma unroll
        for (int i = 0; i < 4; i++) {
            float rm = fmaxf(fmaxf(sc[i][0], sc[i][1]), fmaxf(sc[i][2], sc[i][3]));
#pragma unroll
            for (int off = 8; off >= 1; off >>= 1)
                rm = fmaxf(rm, __shfl_xor_sync(0xffffffffu, rm, off));
            float mnew = fmaxf(mrow[i], rm);
            float alpha = fexp(mrow[i] - mnew);
            float ps = 0.0f;
#pragma unroll
            for (int jj = 0; jj < 4; jj++) {
                sc[i][jj] = fexp(sc[i][jj] - mnew);
                ps += sc[i][jj];
            }
#pragma unroll
            for (int off = 8; off >= 1; off >>= 1)
                ps += __shfl_xor_sync(0xffffffffu, ps, off);
            lrow[i] = lrow[i] * alpha + ps;
            mrow[i] = mnew;
#pragma unroll
            for (int jj = 0; jj < 4; jj++) o[i][jj] *= alpha;
        }

#pragma unroll
        for (int i = 0; i < 4; i++) {
            float4 pv;
            pv.x = sc[i][0]; pv.y = sc[i][1]; pv.z = sc[i][2]; pv.w = sc[i][3];
            *(float4*)&Ps[(ty * 4 + i) * 68 + tx * 4] = pv;
        }
        __syncthreads();

#pragma unroll 4
        for (int k2 = 0; k2 < 64; k2++) {
            float4 v4 = *(const float4*)&Vs[k2 * 64 + tx * 4];
            float va[4] = {v4.x, v4.y, v4.z, v4.w};
#pragma unroll
            for (int i = 0; i < 4; i++) {
                float p = Ps[(ty * 4 + i) * 68 + k2];
#pragma unroll
                for (int jj = 0; jj < 4; jj++) o[i][jj] += p * va[jj];
            }
        }
    }

    // normalize + write bf16 hi/lo split of attn output: [b][s][h*64+c]
    int b = bh >> 4, h = bh & 15;
#pragma unroll
    for (int i = 0; i < 4; i++) {
        int sgl = qb * 64 + ty * 4 + i;
        float inv = 1.0f / lrow[i];
        float r0 = o[i][0] * inv, r1 = o[i][1] * inv;
        float r2 = o[i][2] * inv, r3 = o[i][3] * inv;
        __nv_bfloat16 h0 = __float2bfloat16(r0);
        __nv_bfloat16 h1 = __float2bfloat16(r1);
        __nv_bfloat16 h2 = __float2bfloat16(r2);
        __nv_bfloat16 h3 = __float2bfloat16(r3);
        __nv_bfloat16 l0 = __float2bfloat16(r0 - __bfloat162float(h0));
        __nv_bfloat16 l1 = __float2bfloat16(r1 - __bfloat162float(h1));
        __nv_bfloat16 l2 = __float2bfloat16(r2 - __bfloat162float(h2));
        __nv_bfloat16 l3 = __float2bfloat16(r3 - __bfloat162float(h3));
        size_t base = ((size_t)(b * PS + sgl) * PD) + h * 64 + tx * 4;
        ((__nv_bfloat162*)(g_ah + base))[0] = __halves2bfloat162(h0, h1);
        ((__nv_bfloat162*)(g_ah + base))[1] = __halves2bfloat162(h2, h3);
        ((__nv_bfloat162*)(g_al + base))[0] = __halves2bfloat162(l0, l1);
        ((__nv_bfloat162*)(g_al + base))[1] = __halves2bfloat162(l2, l3);
    }
}

// ---------------------------------------------------------------------------
extern "C" void kernel_launch(void* const* d_in, const int* in_sizes, int n_in,
                              void* d_out, int out_size) {
    const float* x     = (const float*)d_in[0];
    const float* W_qkv = (const float*)d_in[1];
    const float* W_o   = (const float*)d_in[2];
    const int*   tpos  = (const int*)d_in[3];
    float* out = (float*)d_out;

    static const size_t FLASH_SMEM = (size_t)(64*68*2 + 64*64 + 64*68) * sizeof(float);
    cudaFuncSetAttribute(flash_attn_kernel,
                         cudaFuncAttributeMaxDynamicSharedMemorySize, (int)FLASH_SMEM);
    cudaFuncSetAttribute(mma_gemm_kernel<0>,
                         cudaFuncAttributeMaxDynamicSharedMemorySize, GEMM_SMEM);
    cudaFuncSetAttribute(mma_gemm_kernel<1>,
                         cudaFuncAttributeMaxDynamicSharedMemorySize, GEMM_SMEM);

    rope_table_kernel<<<64, 1024>>>(tpos);
    split_x_kernel<<<8192, 256>>>(x);
    split_wq_kernel<<<3072, 256>>>(W_qkv);
    split_wo_kernel<<<1024, 256>>>(W_o);

    mma_gemm_kernel<0><<<dim3(24, 64), 256, GEMM_SMEM>>>(nullptr);   // QKV + RoPE
    flash_attn_kernel<<<dim3(32, 64), 256, FLASH_SMEM>>>();
    mma_gemm_kernel<1><<<dim3(8, 64), 256, GEMM_SMEM>>>(out);        // out proj
}

// round 10
// speedup vs baseline: 1.4855x; 1.4855x over previous
#include <cuda_runtime.h>
#include <cuda_bf16.h>
#include <math.h>
#include <stdint.h>

// Problem constants
#define PB 4
#define PS 2048
#define PD 1024
#define PH 16
#define PDH 64

// ---------------------------------------------------------------------------
// Scratch (device globals — no allocations allowed)
// ---------------------------------------------------------------------------
__device__ float g_cos[PS*32];
__device__ float g_sin[PS*32];

// bf16 split operands
__device__ __nv_bfloat16 g_xh[8192*1024], g_xl[8192*1024];      // x
__device__ __nv_bfloat16 g_wqh[3072*1024], g_wql[3072*1024];    // W_qkv
__device__ __nv_bfloat16 g_woh[1024*1024], g_wol[1024*1024];    // W_o
__device__ __nv_bfloat16 g_ah[8192*1024], g_al[8192*1024];      // attn out
// q/k/v bf16 splits, layout [b*H+h][s][dh]
__device__ __nv_bfloat16 gq_h[PB*PH*PS*PDH], gq_l[PB*PH*PS*PDH];
__device__ __nv_bfloat16 gk_h[PB*PH*PS*PDH], gk_l[PB*PH*PS*PDH];
__device__ __nv_bfloat16 gv_h[PB*PH*PS*PDH], gv_l[PB*PH*PS*PDH];

// ---------------------------------------------------------------------------
// Portable PTX helpers (toolchain targets base compute_103: no tcgen05/TMEM)
// ---------------------------------------------------------------------------
__device__ __forceinline__ uint32_t smem_u32(const void* p) {
    uint32_t a;
    asm("{ .reg .u64 t; cvta.to.shared.u64 t, %1; cvt.u32.u64 %0, t; }"
        : "=r"(a) : "l"(p));
    return a;
}

__device__ __forceinline__ void cp16(uint32_t saddr, const void* gaddr) {
    asm volatile("cp.async.cg.shared.global [%0], [%1], 16;"
                 :: "r"(saddr), "l"(gaddr) : "memory");
}
#define CP_COMMIT() asm volatile("cp.async.commit_group;" ::: "memory")
#define CP_WAIT0()  asm volatile("cp.async.wait_group 0;" ::: "memory")
#define CP_WAIT1()  asm volatile("cp.async.wait_group 1;" ::: "memory")

__device__ __forceinline__ void ldm_x4(uint32_t* r, uint32_t addr) {
    asm volatile("ldmatrix.sync.aligned.m8n8.x4.shared.b16 {%0,%1,%2,%3}, [%4];"
        : "=r"(r[0]), "=r"(r[1]), "=r"(r[2]), "=r"(r[3]) : "r"(addr));
}
__device__ __forceinline__ void ldm_x4_t(uint32_t* r, uint32_t addr) {
    asm volatile("ldmatrix.sync.aligned.m8n8.x4.trans.shared.b16 {%0,%1,%2,%3}, [%4];"
        : "=r"(r[0]), "=r"(r[1]), "=r"(r[2]), "=r"(r[3]) : "r"(addr));
}

__device__ __forceinline__ void mma16816(float* d, const uint32_t* a, const uint32_t* b) {
    asm volatile(
        "mma.sync.aligned.m16n8k16.row.col.f32.bf16.bf16.f32 "
        "{%0,%1,%2,%3}, {%4,%5,%6,%7}, {%8,%9}, {%0,%1,%2,%3};"
        : "+f"(d[0]), "+f"(d[1]), "+f"(d[2]), "+f"(d[3])
        : "r"(a[0]), "r"(a[1]), "r"(a[2]), "r"(a[3]), "r"(b[0]), "r"(b[1]));
}

__device__ __forceinline__ uint32_t bpack(float a, float b) {
    unsigned short la = __bfloat16_as_ushort(__float2bfloat16(a));
    unsigned short lb = __bfloat16_as_ushort(__float2bfloat16(b));
    return (uint32_t)la | ((uint32_t)lb << 16);
}
__device__ __forceinline__ float bhi(float a) {      // value of bf16(a)
    return __bfloat162float(__float2bfloat16(a));
}

// Fast exp on FMA pipe (valid for x <= ~0, clamps at -87)
__device__ __forceinline__ float fexp(float x) {
    float xc = fmaxf(x, -87.0f);
    float t  = fmaf(xc, 1.4426950408889634f, 12582912.0f);
    float n  = t - 12582912.0f;
    float r  = fmaf(n, -0.6931471805599453f, xc);
    float p  = 8.3333333e-3f;
    p = fmaf(p, r, 4.1666667e-2f);
    p = fmaf(p, r, 1.6666667e-1f);
    p = fmaf(p, r, 5.0e-1f);
    p = fmaf(p, r, 1.0f);
    p = fmaf(p, r, 1.0f);
    float s = __int_as_float((__float_as_int(t) << 23) + 0x3f800000);
    return p * s;
}

// ---------------------------------------------------------------------------
// RoPE table (fp64 for fidelity)
// ---------------------------------------------------------------------------
__global__ void rope_table_kernel(const int* __restrict__ pos) {
    int idx = blockIdx.x * blockDim.x + threadIdx.x;   // 65536
    int s = idx >> 5;
    int i = idx & 31;
    double p = (double)pos[s];
    double inv = exp(-((double)(2 * i) / 64.0) * log(10000.0));
    double a = p * inv;
    g_cos[idx] = (float)cos(a);
    g_sin[idx] = (float)sin(a);
}

// ---------------------------------------------------------------------------
// fp32 -> bf16 hi/lo split (2-term); 4 elems/thread
// ---------------------------------------------------------------------------
__device__ __forceinline__ void split4(const float* __restrict__ src,
                                       __nv_bfloat16* __restrict__ hi,
                                       __nv_bfloat16* __restrict__ lo) {
    int i = blockIdx.x * blockDim.x + threadIdx.x;
    float4 v = ((const float4*)src)[i];
    ((uint32_t*)hi)[i*2]   = bpack(v.x, v.y);
    ((uint32_t*)hi)[i*2+1] = bpack(v.z, v.w);
    ((uint32_t*)lo)[i*2]   = bpack(v.x - bhi(v.x), v.y - bhi(v.y));
    ((uint32_t*)lo)[i*2+1] = bpack(v.z - bhi(v.z), v.w - bhi(v.w));
}

__global__ void split_x_kernel(const float* __restrict__ x)  { split4(x, g_xh, g_xl); }
__global__ void split_wq_kernel(const float* __restrict__ w) { split4(w, g_wqh, g_wql); }
__global__ void split_wo_kernel(const float* __restrict__ w) { split4(w, g_woh, g_wol); }

// ---------------------------------------------------------------------------
// mma.sync bf16 GEMM, 128x128 CTA tile, BK=32, 256 threads, 2-stage pipeline.
// MODE 0: A=x, B=W_qkv, epilogue RoPE + bf16-split scatter into gq/gk/gv.
// MODE 1: A=attn(bf16 split), B=W_o, epilogue fp32 store into Cout.
// ---------------------------------------------------------------------------
#define LDT 40
#define TILE_B (128*LDT*2)
#define STAGE_B (4*TILE_B)
#define GEMM_SMEM (2*STAGE_B)

template<int MODE>
__global__ __launch_bounds__(256)
void mma_gemm_kernel(float* __restrict__ Cout)
{
    const __nv_bfloat16 *Ahp, *Alp, *Bhp, *Blp;
    if (MODE == 0) { Ahp = g_xh; Alp = g_xl; Bhp = g_wqh; Blp = g_wql; }
    else           { Ahp = g_ah; Alp = g_al; Bhp = g_woh; Blp = g_wol; }

    extern __shared__ char dsm[];
    const uint32_t sBase = smem_u32(dsm);

    const int tid = threadIdx.x;
    const int n0 = blockIdx.x * 128;
    const int m0 = blockIdx.y * 128;
    const int lane = tid & 31, w = tid >> 5;
    const int wm = w >> 2, wn = w & 3;

    const int lr = tid >> 1, lh = tid & 1;
    const __nv_bfloat16* gAh = Ahp + (size_t)(m0 + lr) * 1024 + lh * 16;
    const __nv_bfloat16* gAl = Alp + (size_t)(m0 + lr) * 1024 + lh * 16;
    const __nv_bfloat16* gBh = Bhp + (size_t)(n0 + lr) * 1024 + lh * 16;
    const __nv_bfloat16* gBl = Blp + (size_t)(n0 + lr) * 1024 + lh * 16;
    const uint32_t sOff = (uint32_t)((lr * LDT + lh * 16) * 2);

    const int quad = lane >> 3, qi = lane & 7;
    const uint32_t aoff = (uint32_t)(((wm*64 + (quad&1)*8 + qi) * LDT + (quad>>1)*8) * 2);
    const uint32_t boff = (uint32_t)(((wn*32 + (quad>>1)*8 + qi) * LDT + (quad&1)*8) * 2);

    float acc[4][4][4];
#pragma unroll
    for (int a = 0; a < 4; a++)
#pragma unroll
        for (int b = 0; b < 4; b++)
#pragma unroll
            for (int c = 0; c < 4; c++) acc[a][b][c] = 0.0f;

    auto load_stage = [&](int kt, int stg) {
        const int kb = kt * 32;
        const uint32_t s0 = sBase + stg * STAGE_B + sOff;
        cp16(s0,                gAh + kb);  cp16(s0 + 16,            gAh + kb + 8);
        cp16(s0 + TILE_B,       gAl + kb);  cp16(s0 + TILE_B + 16,   gAl + kb + 8);
        cp16(s0 + 2*TILE_B,     gBh + kb);  cp16(s0 + 2*TILE_B + 16, gBh + kb + 8);
        cp16(s0 + 3*TILE_B,     gBl + kb);  cp16(s0 + 3*TILE_B + 16, gBl + kb + 8);
        CP_COMMIT();
    };

    load_stage(0, 0);

    for (int kt = 0; kt < 32; kt++) {
        const int stg = kt & 1;
        if (kt + 1 < 32) { load_stage(kt + 1, stg ^ 1); CP_WAIT1(); }
        else CP_WAIT0();
        __syncthreads();

        const uint32_t sAhB = sBase + stg * STAGE_B;
        const uint32_t sAlB = sAhB + TILE_B;
        const uint32_t sBhB = sAhB + 2*TILE_B;
        const uint32_t sBlB = sAhB + 3*TILE_B;

#pragma unroll
        for (int ks = 0; ks < 2; ks++) {
            const uint32_t kso = ks * 32;
            uint32_t aH[4][4], aL[4][4], bH[2][4], bL[2][4];
#pragma unroll
            for (int mt = 0; mt < 4; mt++) {
                ldm_x4(aH[mt], sAhB + aoff + mt * (16*LDT*2) + kso);
                ldm_x4(aL[mt], sAlB + aoff + mt * (16*LDT*2) + kso);
            }
#pragma unroll
            for (int np = 0; np < 2; np++) {
                ldm_x4(bH[np], sBhB + boff + np * (16*LDT*2) + kso);
                ldm_x4(bL[np], sBlB + boff + np * (16*LDT*2) + kso);
            }
#pragma unroll
            for (int mt = 0; mt < 4; mt++)
#pragma unroll
                for (int nt = 0; nt < 4; nt++) {
                    const uint32_t* ph = &bH[nt >> 1][(nt & 1) * 2];
                    const uint32_t* pl = &bL[nt >> 1][(nt & 1) * 2];
                    mma16816(acc[mt][nt], aH[mt], ph);
                    mma16816(acc[mt][nt], aH[mt], pl);
                    mma16816(acc[mt][nt], aL[mt], ph);
                }
        }
        __syncthreads();
    }

    const int g = lane >> 2, tig = lane & 3;
    if (MODE == 0) {
        const int kmat = n0 >> 10;                   // 0=q 1=k 2=v
        __nv_bfloat16* dH = (kmat == 0) ? gq_h : ((kmat == 1) ? gk_h : gv_h);
        __nv_bfloat16* dL = (kmat == 0) ? gq_l : ((kmat == 1) ? gk_l : gv_l);
#pragma unroll
        for (int mt = 0; mt < 4; mt++)
#pragma unroll
            for (int hh = 0; hh < 2; hh++) {
                const int m = m0 + wm*64 + mt*16 + hh*8 + g;
                const int b = m >> 11, s = m & 2047;
#pragma unroll
                for (int nt = 0; nt < 4; nt++) {
                    const int colg = n0 + wn*32 + nt*8 + 2*tig;
                    const int h = (colg >> 6) & 15;
                    const int cc = colg & 63;
                    const float v0 = acc[mt][nt][hh*2];
                    const float v1 = acc[mt][nt][hh*2 + 1];
                    float rx, ry;
                    if (kmat < 2) {
                        const int pi = (s << 5) + (cc >> 1);
                        const float c_ = g_cos[pi], s_ = g_sin[pi];
                        rx = v0 * c_ - v1 * s_;
                        ry = v0 * s_ + v1 * c_;
                    } else {
                        rx = v0; ry = v1;
                    }
                    size_t idx = ((size_t)((b*PH + h)*PS + s))*PDH + cc;
                    *(uint32_t*)(dH + idx) = bpack(rx, ry);
                    *(uint32_t*)(dL + idx) = bpack(rx - bhi(rx), ry - bhi(ry));
                }
            }
    } else {
#pragma unroll
        for (int mt = 0; mt < 4; mt++)
#pragma unroll
            for (int hh = 0; hh < 2; hh++) {
                const int m = m0 + wm*64 + mt*16 + hh*8 + g;
#pragma unroll
                for (int nt = 0; nt < 4; nt++) {
                    const int colg = n0 + wn*32 + nt*8 + 2*tig;
                    float2 r;
                    r.x = acc[mt][nt][hh*2];
                    r.y = acc[mt][nt][hh*2 + 1];
                    *(float2*)(Cout + (size_t)m * 1024 + colg) = r;
                }
            }
    }
}

// ---------------------------------------------------------------------------
// Tensor-core flash attention. q-tile 128 (8 warps x m16), k-tile 64.
// Scores: QhKh + QhKl + QlKh (fp32 acc). Softmax in registers.
// PV: P split in-register (Ph,Pl): PhVh + PlVh + PhVl, V via ldmatrix.trans.
// K/V double-buffered cp.async; Q staged once then register-resident.
// Output written as bf16 hi/lo splits to g_ah/g_al [b][s][h*64+c].
// ---------------------------------------------------------------------------
#define FTILE 9216            // 64 rows * 144 B (72-bf16 stride)
#define FSTG  (4*FTILE)       // Kh,Kl,Vh,Vl = 36864
#define FLASH_SMEM (2*FSTG)   // 73728

__global__ __launch_bounds__(256) void flash_mma_kernel() {
    extern __shared__ char fsm[];
    const uint32_t sb = smem_u32(fsm);
    const int tid = threadIdx.x, lane = tid & 31, w = tid >> 5;
    const int qb = 15 - (int)blockIdx.x;       // heavy CTAs first
    const int bh = blockIdx.y;
    const int quad = lane >> 3, qi = lane & 7;
    const int g = lane >> 2, tig = lane & 3;

    const size_t bhoff = (size_t)bh * PS * PDH;
    const __nv_bfloat16* Kh0 = gk_h + bhoff;
    const __nv_bfloat16* Kl0 = gk_l + bhoff;
    const __nv_bfloat16* Vh0 = gv_h + bhoff;
    const __nv_bfloat16* Vl0 = gv_l + bhoff;

    // ---- stage Q through stage-0 smem, ldmatrix into registers ----
    {
        const int r = tid & 127;
        const __nv_bfloat16* src = (tid < 128 ? gq_h : gq_l) + bhoff + (size_t)(qb*128 + r)*PDH;
        uint32_t dst = sb + (tid < 128 ? 0u : 18432u) + (uint32_t)r*144;
#pragma unroll
        for (int u = 0; u < 8; u++) cp16(dst + u*16, (const char*)src + u*16);
        CP_COMMIT();
    }
    CP_WAIT0();
    __syncthreads();

    uint32_t qH[4][4], qL[4][4];
    {
        const uint32_t ao = (uint32_t)((w*16 + (quad&1)*8 + qi)*144 + (quad>>1)*16);
#pragma unroll
        for (int kd = 0; kd < 4; kd++) {
            ldm_x4(qH[kd], sb + ao + kd*32);
            ldm_x4(qL[kd], sb + 18432 + ao + kd*32);
        }
    }
    __syncthreads();   // stage0 free for K/V

    const int jmax = 2*qb + 1;

    auto load_kv = [&](int j, int stg) {
        const int t = tid >> 6;        // 0 Kh, 1 Kl, 2 Vh, 3 Vl
        const int r = tid & 63;
        const __nv_bfloat16* src =
            (t == 0 ? Kh0 : t == 1 ? Kl0 : t == 2 ? Vh0 : Vl0) + (size_t)(j*64 + r)*PDH;
        uint32_t dst = sb + stg*FSTG + t*FTILE + (uint32_t)r*144;
#pragma unroll
        for (int u = 0; u < 8; u++) cp16(dst + u*16, (const char*)src + u*16);
        CP_COMMIT();
    };

    float o[8][4];
#pragma unroll
    for (int t = 0; t < 8; t++) { o[t][0]=0.f; o[t][1]=0.f; o[t][2]=0.f; o[t][3]=0.f; }
    float m0 = -1e30f, m1 = -1e30f, l0 = 0.f, l1 = 0.f;
    const int row0 = qb*128 + w*16 + g;

    load_kv(0, 0);

    for (int j = 0; j <= jmax; j++) {
        const int stg = j & 1;
        if (j < jmax) { load_kv(j + 1, stg ^ 1); CP_WAIT1(); }
        else CP_WAIT0();
        __syncthreads();

        const uint32_t KhB = sb + stg*FSTG;
        const uint32_t KlB = KhB + FTILE;
        const uint32_t VhB = KhB + 2*FTILE;
        const uint32_t VlB = KhB + 3*FTILE;

        // ---- QK^T ----
        float sc[8][4];
#pragma unroll
        for (int t = 0; t < 8; t++) { sc[t][0]=0.f; sc[t][1]=0.f; sc[t][2]=0.f; sc[t][3]=0.f; }

        const uint32_t bo = (uint32_t)(((quad>>1)*8 + qi)*144 + (quad&1)*16);
#pragma unroll
        for (int kd = 0; kd < 4; kd++) {
            uint32_t bKh[4][4], bKl[4][4];
#pragma unroll
            for (int p = 0; p < 4; p++) {
                ldm_x4(bKh[p], KhB + bo + p*(16*144) + kd*32);
                ldm_x4(bKl[p], KlB + bo + p*(16*144) + kd*32);
            }
#pragma unroll
            for (int t = 0; t < 8; t++) {
                const uint32_t* ph = &bKh[t>>1][(t&1)*2];
                const uint32_t* pl = &bKl[t>>1][(t&1)*2];
                mma16816(sc[t], qH[kd], ph);
                mma16816(sc[t], qH[kd], pl);
                mma16816(sc[t], qL[kd], ph);
            }
        }

        // ---- scale + causal mask ----
        if (j*64 + 63 > qb*128 + w*16) {
#pragma unroll
            for (int t = 0; t < 8; t++) {
                const int colb = j*64 + t*8 + 2*tig;
#pragma unroll
                for (int e = 0; e < 4; e++) {
                    const int col = colb + (e & 1);
                    const int row = row0 + ((e >= 2) ? 8 : 0);
                    sc[t][e] = (col > row) ? -1e30f : sc[t][e] * 0.125f;
                }
            }
        } else {
#pragma unroll
            for (int t = 0; t < 8; t++) {
                sc[t][0] *= 0.125f; sc[t][1] *= 0.125f;
                sc[t][2] *= 0.125f; sc[t][3] *= 0.125f;
            }
        }

        // ---- online softmax (rows g and g+8) ----
        float rm0 = -1e30f, rm1 = -1e30f;
#pragma unroll
        for (int t = 0; t < 8; t++) {
            rm0 = fmaxf(rm0, fmaxf(sc[t][0], sc[t][1]));
            rm1 = fmaxf(rm1, fmaxf(sc[t][2], sc[t][3]));
        }
        rm0 = fmaxf(rm0, __shfl_xor_sync(0xffffffffu, rm0, 1));
        rm0 = fmaxf(rm0, __shfl_xor_sync(0xffffffffu, rm0, 2));
        rm1 = fmaxf(rm1, __shfl_xor_sync(0xffffffffu, rm1, 1));
        rm1 = fmaxf(rm1, __shfl_xor_sync(0xffffffffu, rm1, 2));
        const float mn0 = fmaxf(m0, rm0), mn1 = fmaxf(m1, rm1);
        const float a0 = fexp(m0 - mn0), a1 = fexp(m1 - mn1);
        float s0 = 0.f, s1 = 0.f;
#pragma unroll
        for (int t = 0; t < 8; t++) {
            sc[t][0] = fexp(sc[t][0] - mn0); sc[t][1] = fexp(sc[t][1] - mn0);
            sc[t][2] = fexp(sc[t][2] - mn1); sc[t][3] = fexp(sc[t][3] - mn1);
            s0 += sc[t][0] + sc[t][1];
            s1 += sc[t][2] + sc[t][3];
        }
        s0 += __shfl_xor_sync(0xffffffffu, s0, 1);
        s0 += __shfl_xor_sync(0xffffffffu, s0, 2);
        s1 += __shfl_xor_sync(0xffffffffu, s1, 1);
        s1 += __shfl_xor_sync(0xffffffffu, s1, 2);
        l0 = l0 * a0 + s0; l1 = l1 * a1 + s1;
        m0 = mn0; m1 = mn1;
#pragma unroll
        for (int t = 0; t < 8; t++) {
            o[t][0] *= a0; o[t][1] *= a0; o[t][2] *= a1; o[t][3] *= a1;
        }

        // ---- PV: in-register P split, V via ldmatrix.trans ----
        const uint32_t vo = (uint32_t)(((quad&1)*8 + qi)*144 + (quad>>1)*16);
#pragma unroll
        for (int kk = 0; kk < 4; kk++) {
            const int t0 = 2*kk, t1 = 2*kk + 1;
            uint32_t aph[4], apl[4];
            aph[0] = bpack(sc[t0][0], sc[t0][1]);
            aph[1] = bpack(sc[t0][2], sc[t0][3]);
            aph[2] = bpack(sc[t1][0], sc[t1][1]);
            aph[3] = bpack(sc[t1][2], sc[t1][3]);
            apl[0] = bpack(sc[t0][0]-bhi(sc[t0][0]), sc[t0][1]-bhi(sc[t0][1]));
            apl[1] = bpack(sc[t0][2]-bhi(sc[t0][2]), sc[t0][3]-bhi(sc[t0][3]));
            apl[2] = bpack(sc[t1][0]-bhi(sc[t1][0]), sc[t1][1]-bhi(sc[t1][1]));
            apl[3] = bpack(sc[t1][2]-bhi(sc[t1][2]), sc[t1][3]-bhi(sc[t1][3]));

            uint32_t bVh[4][4], bVl[4][4];
#pragma unroll
            for (int dp = 0; dp < 4; dp++) {
                ldm_x4_t(bVh[dp], VhB + vo + kk*(16*144) + dp*32);
                ldm_x4_t(bVl[dp], VlB + vo + kk*(16*144) + dp*32);
            }
#pragma unroll
            for (int dt = 0; dt < 8; dt++) {
                const uint32_t* ph = &bVh[dt>>1][(dt&1)*2];
                const uint32_t* pl = &bVl[dt>>1][(dt&1)*2];
                mma16816(o[dt], aph, ph);
                mma16816(o[dt], apl, ph);
                mma16816(o[dt], aph, pl);
            }
        }
        __syncthreads();
    }

    // ---- epilogue: normalize, write bf16 hi/lo attn output ----
    const float inv0 = 1.0f / l0, inv1 = 1.0f / l1;
    const int b = bh >> 4, h = bh & 15;
    const int s0r = qb*128 + w*16 + g;
    const int s1r = s0r + 8;
#pragma unroll
    for (int t = 0; t < 8; t++) {
        const float x0 = o[t][0]*inv0, x1 = o[t][1]*inv0;
        const float y0 = o[t][2]*inv1, y1 = o[t][3]*inv1;
        const int col = h*64 + t*8 + 2*tig;
        const size_t i0 = ((size_t)(b*PS + s0r))*PD + col;
        const size_t i1 = ((size_t)(b*PS + s1r))*PD + col;
        *(uint32_t*)(g_ah + i0) = bpack(x0, x1);
        *(uint32_t*)(g_al + i0) = bpack(x0 - bhi(x0), x1 - bhi(x1));
        *(uint32_t*)(g_ah + i1) = bpack(y0, y1);
        *(uint32_t*)(g_al + i1) = bpack(y0 - bhi(y0), y1 - bhi(y1));
    }
}

// ---------------------------------------------------------------------------
extern "C" void kernel_launch(void* const* d_in, const int* in_sizes, int n_in,
                              void* d_out, int out_size) {
    const float* x     = (const float*)d_in[0];
    const float* W_qkv = (const float*)d_in[1];
    const float* W_o   = (const float*)d_in[2];
    const int*   tpos  = (const int*)d_in[3];
    float* out = (float*)d_out;

    cudaFuncSetAttribute(flash_mma_kernel,
                         cudaFuncAttributeMaxDynamicSharedMemorySize, FLASH_SMEM);
    cudaFuncSetAttribute(mma_gemm_kernel<0>,
                         cudaFuncAttributeMaxDynamicSharedMemorySize, GEMM_SMEM);
    cudaFuncSetAttribute(mma_gemm_kernel<1>,
                         cudaFuncAttributeMaxDynamicSharedMemorySize, GEMM_SMEM);

    rope_table_kernel<<<64, 1024>>>(tpos);
    split_x_kernel<<<8192, 256>>>(x);
    split_wq_kernel<<<3072, 256>>>(W_qkv);
    split_wo_kernel<<<1024, 256>>>(W_o);

    mma_gemm_kernel<0><<<dim3(24, 64), 256, GEMM_SMEM>>>(nullptr);   // QKV + RoPE + splits
    flash_mma_kernel<<<dim3(16, 64), 256, FLASH_SMEM>>>();
    mma_gemm_kernel<1><<<dim3(8, 64), 256, GEMM_SMEM>>>(out);        // out proj
}